// round 11
// baseline (speedup 1.0000x reference)
#include <cuda_runtime.h>
#include <math.h>

#define HD    4096
#define NBLK  148
#define NTHR  1024
#define NWARP (NTHR / 32)
#define MAXS  16
#define PF4   256    // float4 per W_out row prefetched during the idle window

// Persistent-kernel state (allocation-free scratch).
__device__ float g_h[2][HD];             // double-buffered hidden state
__device__ float g_part[MAXS][NBLK];     // per-step per-block halt partial sums
__device__ unsigned g_barcnt;            // grid barrier arrival count
__device__ volatile unsigned g_bargen;   // grid barrier generation

__device__ __forceinline__ void grid_barrier() {
    __syncthreads();
    if (threadIdx.x == 0) {
        __threadfence();                       // release
        unsigned gen = g_bargen;
        if (atomicAdd(&g_barcnt, 1u) == NBLK - 1u) {
            g_barcnt = 0u;
            __threadfence();
            g_bargen = gen + 1u;
        } else {
            while (g_bargen == gen) { __nanosleep(32); }
        }
        __threadfence();                       // acquire
    }
    __syncthreads();
}

__device__ __forceinline__ float warp_red(float v) {
#pragma unroll
    for (int o = 16; o; o >>= 1) v += __shfl_xor_sync(0xffffffffu, v, o);
    return v;   // full sum on all lanes
}

__device__ __forceinline__ void pf_l2(const void* p) {
    asm volatile("prefetch.global.L2 [%0];" :: "l"(p));
}

__global__ void __launch_bounds__(NTHR, 1) arnn_kernel(
    const float* __restrict__ x,     const float* __restrict__ s,
    const float* __restrict__ W_ih,  const float* __restrict__ b_ih,
    const float* __restrict__ W_hh,  const float* __restrict__ b_hh,
    const float* __restrict__ w_halt,const float* __restrict__ b_halt,
    const float* __restrict__ W_out, const float* __restrict__ b_out,
    float* __restrict__ out)
{
    __shared__ float sx[HD];          // staged x (16 KB)
    __shared__ float sv[HD];          // staged h / s  (16 KB)
    __shared__ float red[NWARP];      // per-warp halt contributions
    __shared__ float bc;              // halt-sum broadcast

    const int tid  = threadIdx.x;
    const int lane = tid & 31;
    const int warp = tid >> 5;
    const int b    = blockIdx.x;

    // Balanced contiguous row ranges: every block gets 27-28 rows.
    const int r0    = (HD * b) / NBLK;
    const int r1    = (HD * (b + 1)) / NBLK;
    const int nrows = r1 - r0;
    const bool has_row = (warp < nrows);
    const int r     = r0 + warp;

    // Per-lane slice of this warp's W_hh row, held in REGISTERS across steps.
    // All indexing below is fully unrolled (static) — any dynamic index spills.
    float4 wreg[32];

    // ---- Stage x and s once (vectorized) ----
    {
        const float4* x4 = (const float4*)x;
        const float4* s4 = (const float4*)s;
        float4* sx4 = (float4*)sx;
        float4* sv4 = (float4*)sv;
        for (int i = tid; i < HD / 4; i += NTHR) { sx4[i] = x4[i]; sv4[i] = s4[i]; }
    }
    __syncthreads();

    const float bhalt = b_halt[0];
    float z_reg = 0.f, whalt_reg = 0.f;

    // ---- Fused phase-0 + step-0, dual-stream interleaved; W_hh row is parked
    //      in registers as it streams by (step >= 1 then needs NO weight loads):
    //      z  = W_ih[:,1:] @ x + b_ih + b_hh
    //      a0 = W_hh @ s ;  h0 = tanh(z + W_ih[:,0] + a0)
    if (has_row) {
        const float* rowp = W_ih + (size_t)r * (HD + 1) + 1;   // misaligned by (r+1)&3
        const int mis  = (int)(((size_t)rowp >> 2) & 3);
        const int lead = (4 - mis) & 3;
        const float4* vA   = (const float4*)(rowp + lead);
        const float4* rowB = (const float4*)(W_hh + (size_t)r * HD);
        const float4* sv4  = (const float4*)sv;
        const int nA = (HD - lead) >> 2;                        // 1023 or 1024

        float accA = 0.f, accB = 0.f;
        if (lane < lead) accA = fmaf(__ldcs(rowp + lane), sx[lane], accA);

#pragma unroll
        for (int k = 0; k < 31; k++) {            // idx <= 991 < nA always
            const int idx = 32 * k + lane;
            float4 wb = __ldcs(rowB + idx);
            wreg[k] = wb;
            float4 h4 = sv4[idx];
            accB = fmaf(wb.x, h4.x, accB);
            accB = fmaf(wb.y, h4.y, accB);
            accB = fmaf(wb.z, h4.z, accB);
            accB = fmaf(wb.w, h4.w, accB);
            float4 wa = __ldcs(vA + idx);
            const int j = lead + 4 * idx;
            accA = fmaf(wa.x, sx[j + 0], accA);
            accA = fmaf(wa.y, sx[j + 1], accA);
            accA = fmaf(wa.z, sx[j + 2], accA);
            accA = fmaf(wa.w, sx[j + 3], accA);
        }
        {   // k = 31: B always, A predicated on idx < nA
            const int idx = 992 + lane;
            float4 wb = __ldcs(rowB + idx);
            wreg[31] = wb;
            float4 h4 = sv4[idx];
            accB = fmaf(wb.x, h4.x, accB);
            accB = fmaf(wb.y, h4.y, accB);
            accB = fmaf(wb.z, h4.z, accB);
            accB = fmaf(wb.w, h4.w, accB);
            if (idx < nA) {
                float4 wa = __ldcs(vA + idx);
                const int j = lead + 4 * idx;
                accA = fmaf(wa.x, sx[j + 0], accA);
                accA = fmaf(wa.y, sx[j + 1], accA);
                accA = fmaf(wa.z, sx[j + 2], accA);
                accA = fmaf(wa.w, sx[j + 3], accA);
            }
        }
        const int ts = lead + 4 * nA;
        if (lane < HD - ts) accA = fmaf(__ldcs(rowp + ts + lane), sx[ts + lane], accA);

        accA = warp_red(accA);
        accB = warp_red(accB);
        z_reg     = accA + b_ih[r] + b_hh[r];
        whalt_reg = w_halt[r];
        if (lane == 0) {
            float hn = tanhf(z_reg + __ldcs(rowp - 1) + accB);
            __stcg(&g_h[0][r], hn);
            red[warp] = whalt_reg * hn;
        }
    } else if (lane == 0) {
        red[warp] = 0.f;
    }
    __syncthreads();
    if (tid == 0) {                     // fixed-order per-block partial
        float p = 0.f;
        for (int w = 0; w < nrows; w++) p += red[w];
        __stcg(&g_part[0][b], p);
    }
    grid_barrier();

    float cum = 0.f;
    int   t   = 0;

    for (;;) {
        // ---- Deterministic replicated halt decision ----
        if (warp == 0) {
            float a = 0.f;
#pragma unroll
            for (int i = lane; i < NBLK; i += 32) a += __ldcg(&g_part[t][i]);
            a = warp_red(a);
            if (lane == 0) bc = a;
        }
        __syncthreads();
        {
            float p = 1.f / (1.f + expf(-(bc + bhalt)));
            cum += p;
            if (cum >= 0.99f || t == MAXS - 1) break;
        }
        t++;

        // ---- Small W_out head prefetch in the (short) DRAM-idle window ----
        if (t == 1) {
            const char* base = (const char*)(W_out + (size_t)r0 * HD);
            const int lines = PF4 / 8;                       // 128B lines per row
            for (int i = tid; i < nrows * lines; i += NTHR) {
                const int w = i / lines, l = i % lines;
                pf_l2(base + (size_t)w * HD * 4 + (size_t)l * 128);
            }
        }

        // ---- Step t >= 1: h_t = tanh(z + W_hh @ h_{t-1}) — W_hh from REGISTERS ----
        __syncthreads();
        {
            const float4* hold = (const float4*)g_h[(t - 1) & 1];
            float4* sv4 = (float4*)sv;
            for (int i = tid; i < HD / 4; i += NTHR) sv4[i] = __ldcg(&hold[i]);
        }
        __syncthreads();

        if (has_row) {
            const float4* hv4 = (const float4*)sv;
            float ah = 0.f;
#pragma unroll
            for (int k = 0; k < 32; k++) {
                const int idx = 32 * k + lane;
                float4 w  = wreg[k];
                float4 h4 = hv4[idx];
                ah = fmaf(w.x, h4.x, ah);
                ah = fmaf(w.y, h4.y, ah);
                ah = fmaf(w.z, h4.z, ah);
                ah = fmaf(w.w, h4.w, ah);
            }
            ah = warp_red(ah);
            if (lane == 0) {
                float hn = tanhf(z_reg + ah);
                __stcg(&g_h[t & 1][r], hn);
                red[warp] = whalt_reg * hn;
            }
        } else if (lane == 0) {
            red[warp] = 0.f;
        }

        __syncthreads();
        if (tid == 0) {
            float p = 0.f;
            for (int w = 0; w < nrows; w++) p += red[w];
            __stcg(&g_part[t][b], p);
        }
        grid_barrier();
    }

    // ---- Final: output = W_out @ h[t] + b_out ; s_new = h[t] ; ponder = t ----
    __syncthreads();
    const float* hf = g_h[t & 1];
    {
        const float4* hf4 = (const float4*)hf;
        float4* sv4 = (float4*)sv;
        for (int i = tid; i < HD / 4; i += NTHR) sv4[i] = __ldcg(&hf4[i]);
    }
    __syncthreads();

    if (has_row) {
        const float4* row = (const float4*)(W_out + (size_t)r * HD);
        const float4* hv4 = (const float4*)sv;
        float acc = 0.f;
#pragma unroll 8
        for (int i = lane; i < HD / 4; i += 32) {
            float4 w  = __ldcs(row + i);   // read-once demand stream
            float4 h4 = hv4[i];
            acc = fmaf(w.x, h4.x, acc);
            acc = fmaf(w.y, h4.y, acc);
            acc = fmaf(w.z, h4.z, acc);
            acc = fmaf(w.w, h4.w, acc);
        }
        acc = warp_red(acc);
        if (lane == 0) out[r] = acc + b_out[r];
    }
    if (b == 0) {
        for (int i = tid; i < HD; i += NTHR) out[HD + i] = sv[i];
        if (tid == 0) out[2 * HD] = (float)t;
    }
}

extern "C" void kernel_launch(void* const* d_in, const int* in_sizes, int n_in,
                              void* d_out, int out_size) {
    (void)in_sizes; (void)n_in; (void)out_size;
    arnn_kernel<<<NBLK, NTHR>>>(
        (const float*)d_in[0],  // x
        (const float*)d_in[1],  // s
        (const float*)d_in[2],  // W_ih
        (const float*)d_in[3],  // b_ih
        (const float*)d_in[4],  // W_hh
        (const float*)d_in[5],  // b_hh
        (const float*)d_in[6],  // w_halt
        (const float*)d_in[7],  // b_halt
        (const float*)d_in[8],  // W_out
        (const float*)d_in[9],  // b_out
        (float*)d_out);
}

// round 12
// speedup vs baseline: 1.2749x; 1.2749x over previous
#include <cuda_runtime.h>
#include <math.h>

#define HD    4096
#define NBLK  152    // GB300 has 152 SMs (not 148) — one persistent CTA per SM
#define NTHR  1024
#define NWARP (NTHR / 32)
#define MAXS  16

// Persistent-kernel state (allocation-free scratch).
__device__ float g_h[2][HD];             // double-buffered hidden state
__device__ float g_part[MAXS][NBLK];     // per-step per-block halt partial sums
__device__ unsigned g_barcnt;            // grid barrier arrival count
__device__ volatile unsigned g_bargen;   // grid barrier generation

__device__ __forceinline__ void grid_barrier() {
    __syncthreads();
    if (threadIdx.x == 0) {
        __threadfence();                       // release
        unsigned gen = g_bargen;
        if (atomicAdd(&g_barcnt, 1u) == NBLK - 1u) {
            g_barcnt = 0u;
            __threadfence();
            g_bargen = gen + 1u;
        } else {
            while (g_bargen == gen) { __nanosleep(32); }
        }
        __threadfence();                       // acquire
    }
    __syncthreads();
}

__device__ __forceinline__ float warp_red(float v) {
#pragma unroll
    for (int o = 16; o; o >>= 1) v += __shfl_xor_sync(0xffffffffu, v, o);
    return v;   // full sum on all lanes
}

__device__ __forceinline__ void pf_l2(const void* p) {
    asm volatile("prefetch.global.L2 [%0];" :: "l"(p));
}

__global__ void __launch_bounds__(NTHR, 1) arnn_kernel(
    const float* __restrict__ x,     const float* __restrict__ s,
    const float* __restrict__ W_ih,  const float* __restrict__ b_ih,
    const float* __restrict__ W_hh,  const float* __restrict__ b_hh,
    const float* __restrict__ w_halt,const float* __restrict__ b_halt,
    const float* __restrict__ W_out, const float* __restrict__ b_out,
    float* __restrict__ out)
{
    __shared__ float sx[HD];          // staged x (16 KB)
    __shared__ float sv[HD];          // staged h / s  (16 KB)
    __shared__ float red[NWARP];      // per-warp halt contributions
    __shared__ float bc;              // halt-sum broadcast

    const int tid  = threadIdx.x;
    const int lane = tid & 31;
    const int warp = tid >> 5;
    const int b    = blockIdx.x;

    // Balanced contiguous row ranges: every block gets 26-27 rows.
    const int r0    = (HD * b) / NBLK;
    const int r1    = (HD * (b + 1)) / NBLK;
    const int nrows = r1 - r0;
    const bool has_row = (warp < nrows);
    const int r     = r0 + warp;

    // ---- Stage x and s once (vectorized) ----
    {
        const float4* x4 = (const float4*)x;
        const float4* s4 = (const float4*)s;
        float4* sx4 = (float4*)sx;
        float4* sv4 = (float4*)sv;
        for (int i = tid; i < HD / 4; i += NTHR) { sx4[i] = x4[i]; sv4[i] = s4[i]; }
    }
    __syncthreads();

    const float bhalt = b_halt[0];
    float z_reg = 0.f, whalt_reg = 0.f;

    // ---- Fused phase-0 + step-0, dual-stream interleaved:
    //      z  = W_ih[:,1:] @ x + b_ih + b_hh   (evict-first stream)
    //      a0 = W_hh @ s                        (default: stays in L2 for step 1)
    //      h0 = tanh(z + W_ih[:,0] + a0)
    if (has_row) {
        const float* rowp = W_ih + (size_t)r * (HD + 1) + 1;   // misaligned by (r+1)&3
        const int mis  = (int)(((size_t)rowp >> 2) & 3);
        const int lead = (4 - mis) & 3;
        const float4* vA   = (const float4*)(rowp + lead);
        const float4* rowB = (const float4*)(W_hh + (size_t)r * HD);
        const float4* sv4  = (const float4*)sv;
        const int nA = (HD - lead) >> 2;                        // 1023 or 1024

        float accA = 0.f, accB = 0.f;
        if (lane < lead) accA = fmaf(__ldcs(rowp + lane), sx[lane], accA);

        // Branch-free main body: 992 vectors of each stream (31 iters/lane).
#pragma unroll 4
        for (int i = lane; i < 992; i += 32) {
            float4 wb = rowB[i];
            float4 h4 = sv4[i];
            accB = fmaf(wb.x, h4.x, accB);
            accB = fmaf(wb.y, h4.y, accB);
            accB = fmaf(wb.z, h4.z, accB);
            accB = fmaf(wb.w, h4.w, accB);
            float4 wa = __ldcs(vA + i);
            const int j = lead + 4 * i;
            accA = fmaf(wa.x, sx[j + 0], accA);
            accA = fmaf(wa.y, sx[j + 1], accA);
            accA = fmaf(wa.z, sx[j + 2], accA);
            accA = fmaf(wa.w, sx[j + 3], accA);
        }
        // Tail: B has 1024 vectors, A has 1023 (lead>0) or 1024 (lead==0).
        {
            const int i = 992 + lane;   // 992..1023
            float4 wb = rowB[i];
            float4 h4 = sv4[i];
            accB = fmaf(wb.x, h4.x, accB);
            accB = fmaf(wb.y, h4.y, accB);
            accB = fmaf(wb.z, h4.z, accB);
            accB = fmaf(wb.w, h4.w, accB);
            if (i < nA) {
                float4 wa = __ldcs(vA + i);
                const int j = lead + 4 * i;
                accA = fmaf(wa.x, sx[j + 0], accA);
                accA = fmaf(wa.y, sx[j + 1], accA);
                accA = fmaf(wa.z, sx[j + 2], accA);
                accA = fmaf(wa.w, sx[j + 3], accA);
            }
        }
        const int ts = lead + 4 * nA;
        if (lane < HD - ts) accA = fmaf(__ldcs(rowp + ts + lane), sx[ts + lane], accA);

        accA = warp_red(accA);
        accB = warp_red(accB);
        z_reg     = accA + b_ih[r] + b_hh[r];
        whalt_reg = w_halt[r];
        if (lane == 0) {
            float hn = tanhf(z_reg + __ldcs(rowp - 1) + accB);
            __stcg(&g_h[0][r], hn);
            red[warp] = whalt_reg * hn;
        }
    } else if (lane == 0) {
        red[warp] = 0.f;
    }
    __syncthreads();
    if (tid == 0) {                     // fixed-order per-block partial
        float p = 0.f;
        for (int w = 0; w < nrows; w++) p += red[w];
        __stcg(&g_part[0][b], p);
    }
    grid_barrier();

    float cum = 0.f;
    int   t   = 0;

    for (;;) {
        // ---- Deterministic replicated halt decision ----
        if (warp == 0) {
            float a = 0.f;
#pragma unroll
            for (int i = lane; i < NBLK; i += 32) a += __ldcg(&g_part[t][i]);
            a = warp_red(a);
            if (lane == 0) bc = a;
        }
        __syncthreads();
        {
            float p = 1.f / (1.f + expf(-(bc + bhalt)));
            cum += p;
            if (cum >= 0.99f || t == MAXS - 1) break;
        }
        t++;

        // ---- W_out L2 prefetch, once, AFTER burst-A demand has drained:
        //      streams during the DRAM-idle step-1 window. ----
        if (t == 1) {
            const char* base = (const char*)(W_out + (size_t)r0 * HD);
            const size_t span = (size_t)nrows * HD * sizeof(float);
            for (size_t off = (size_t)tid * 128; off < span; off += (size_t)NTHR * 128)
                pf_l2(base + off);
        }

        // ---- Step t >= 1: h_t = tanh(z + W_hh @ h_{t-1})  (W_hh from L2) ----
        __syncthreads();
        {
            const float4* hold = (const float4*)g_h[(t - 1) & 1];
            float4* sv4 = (float4*)sv;
            for (int i = tid; i < HD / 4; i += NTHR) sv4[i] = __ldcg(&hold[i]);
        }
        __syncthreads();

        if (has_row) {
            const float4* row = (const float4*)(W_hh + (size_t)r * HD);
            const float4* hv4 = (const float4*)sv;
            float ah0 = 0.f, ah1 = 0.f;           // dual accumulators: shorter
#pragma unroll 8                                   // FMA dependency chains
            for (int i = lane; i < HD / 4; i += 64) {
                float4 w  = row[i];
                float4 h4 = hv4[i];
                ah0 = fmaf(w.x, h4.x, ah0);
                ah0 = fmaf(w.y, h4.y, ah0);
                ah0 = fmaf(w.z, h4.z, ah0);
                ah0 = fmaf(w.w, h4.w, ah0);
                float4 w2  = row[i + 32];
                float4 h42 = hv4[i + 32];
                ah1 = fmaf(w2.x, h42.x, ah1);
                ah1 = fmaf(w2.y, h42.y, ah1);
                ah1 = fmaf(w2.z, h42.z, ah1);
                ah1 = fmaf(w2.w, h42.w, ah1);
            }
            float ah = warp_red(ah0 + ah1);
            if (lane == 0) {
                float hn = tanhf(z_reg + ah);
                __stcg(&g_h[t & 1][r], hn);
                red[warp] = whalt_reg * hn;
            }
        } else if (lane == 0) {
            red[warp] = 0.f;
        }

        __syncthreads();
        if (tid == 0) {
            float p = 0.f;
            for (int w = 0; w < nrows; w++) p += red[w];
            __stcg(&g_part[t][b], p);
        }
        grid_barrier();
    }

    // ---- Final: output = W_out @ h[t] + b_out ; s_new = h[t] ; ponder = t ----
    __syncthreads();
    const float* hf = g_h[t & 1];
    {
        const float4* hf4 = (const float4*)hf;
        float4* sv4 = (float4*)sv;
        for (int i = tid; i < HD / 4; i += NTHR) sv4[i] = __ldcg(&hf4[i]);
    }
    __syncthreads();

    if (has_row) {
        const float4* row = (const float4*)(W_out + (size_t)r * HD);
        const float4* hv4 = (const float4*)sv;
        float acc = 0.f;
#pragma unroll 8
        for (int i = lane; i < HD / 4; i += 32) {
            float4 w  = __ldcs(row + i);   // read-once; hits L2 via tail prefetch
            float4 h4 = hv4[i];
            acc = fmaf(w.x, h4.x, acc);
            acc = fmaf(w.y, h4.y, acc);
            acc = fmaf(w.z, h4.z, acc);
            acc = fmaf(w.w, h4.w, acc);
        }
        acc = warp_red(acc);
        if (lane == 0) out[r] = acc + b_out[r];
    }
    if (b == 0) {
        for (int i = tid; i < HD; i += NTHR) out[HD + i] = sv[i];
        if (tid == 0) out[2 * HD] = (float)t;
    }
}

extern "C" void kernel_launch(void* const* d_in, const int* in_sizes, int n_in,
                              void* d_out, int out_size) {
    (void)in_sizes; (void)n_in; (void)out_size;
    arnn_kernel<<<NBLK, NTHR>>>(
        (const float*)d_in[0],  // x
        (const float*)d_in[1],  // s
        (const float*)d_in[2],  // W_ih
        (const float*)d_in[3],  // b_ih
        (const float*)d_in[4],  // W_hh
        (const float*)d_in[5],  // b_hh
        (const float*)d_in[6],  // w_halt
        (const float*)d_in[7],  // b_halt
        (const float*)d_in[8],  // W_out
        (const float*)d_in[9],  // b_out
        (float*)d_out);
}

// round 13
// speedup vs baseline: 1.2790x; 1.0032x over previous
#include <cuda_runtime.h>
#include <math.h>

#define HD    4096
#define NBLK  148    // proven co-resident count; 152 regressed (R12)
#define NTHR  1024
#define NWARP (NTHR / 32)
#define MAXS  16

// Persistent-kernel state (allocation-free scratch).
__device__ float g_h[2][HD];             // double-buffered hidden state
__device__ float g_part[MAXS][NBLK];     // per-step per-block halt partial sums
__device__ unsigned g_barcnt;            // grid barrier arrival count
__device__ volatile unsigned g_bargen;   // grid barrier generation

__device__ __forceinline__ void grid_barrier() {
    __syncthreads();
    if (threadIdx.x == 0) {
        __threadfence();                       // release
        unsigned gen = g_bargen;
        if (atomicAdd(&g_barcnt, 1u) == NBLK - 1u) {
            g_barcnt = 0u;
            __threadfence();
            g_bargen = gen + 1u;
        } else {
            while (g_bargen == gen) { __nanosleep(16); }
        }
        __threadfence();                       // acquire
    }
    __syncthreads();
}

__device__ __forceinline__ float warp_red(float v) {
#pragma unroll
    for (int o = 16; o; o >>= 1) v += __shfl_xor_sync(0xffffffffu, v, o);
    return v;   // full sum on all lanes
}

__device__ __forceinline__ void pf_l2(const void* p) {
    asm volatile("prefetch.global.L2 [%0];" :: "l"(p));
}

__global__ void __launch_bounds__(NTHR, 1) arnn_kernel(
    const float* __restrict__ x,     const float* __restrict__ s,
    const float* __restrict__ W_ih,  const float* __restrict__ b_ih,
    const float* __restrict__ W_hh,  const float* __restrict__ b_hh,
    const float* __restrict__ w_halt,const float* __restrict__ b_halt,
    const float* __restrict__ W_out, const float* __restrict__ b_out,
    float* __restrict__ out)
{
    __shared__ float sx[HD];          // staged x (16 KB)
    __shared__ float sv[HD];          // staged h / s  (16 KB)
    __shared__ float red[NWARP];      // per-warp halt contributions
    __shared__ float bc;              // halt-sum broadcast

    const int tid  = threadIdx.x;
    const int lane = tid & 31;
    const int warp = tid >> 5;
    const int b    = blockIdx.x;

    // Balanced contiguous row ranges: every block gets 27-28 rows.
    const int r0    = (HD * b) / NBLK;
    const int r1    = (HD * (b + 1)) / NBLK;
    const int nrows = r1 - r0;
    const bool has_row = (warp < nrows);
    const int r     = r0 + warp;

    // ---- Stage x and s once (vectorized) ----
    {
        const float4* x4 = (const float4*)x;
        const float4* s4 = (const float4*)s;
        float4* sx4 = (float4*)sx;
        float4* sv4 = (float4*)sv;
        for (int i = tid; i < HD / 4; i += NTHR) { sx4[i] = x4[i]; sv4[i] = s4[i]; }
    }
    __syncthreads();

    const float bhalt = b_halt[0];
    float z_reg = 0.f, whalt_reg = 0.f;

    // ---- Fused phase-0 + step-0, dual-stream interleaved, split accumulators:
    //      z  = W_ih[:,1:] @ x + b_ih + b_hh   (evict-first stream)
    //      a0 = W_hh @ s                        (default: stays in L2 for step 1)
    //      h0 = tanh(z + W_ih[:,0] + a0)
    if (has_row) {
        const float* rowp = W_ih + (size_t)r * (HD + 1) + 1;   // misaligned by (r+1)&3
        const int mis  = (int)(((size_t)rowp >> 2) & 3);
        const int lead = (4 - mis) & 3;
        const float4* vA   = (const float4*)(rowp + lead);
        const float4* rowB = (const float4*)(W_hh + (size_t)r * HD);
        const float4* sv4  = (const float4*)sv;
        const int nA = (HD - lead) >> 2;                        // 1023 or 1024

        float accA0 = 0.f, accA1 = 0.f, accB0 = 0.f, accB1 = 0.f;
        if (lane < lead) accA0 = fmaf(__ldcs(rowp + lane), sx[lane], accA0);

        // Branch-free main body: 960 vectors per stream (15 iters of 64/lane).
#pragma unroll 3
        for (int i = lane; i < 960; i += 64) {
            float4 wb0 = rowB[i];
            float4 h40 = sv4[i];
            accB0 = fmaf(wb0.x, h40.x, accB0);
            accB0 = fmaf(wb0.y, h40.y, accB0);
            accB0 = fmaf(wb0.z, h40.z, accB0);
            accB0 = fmaf(wb0.w, h40.w, accB0);
            float4 wb1 = rowB[i + 32];
            float4 h41 = sv4[i + 32];
            accB1 = fmaf(wb1.x, h41.x, accB1);
            accB1 = fmaf(wb1.y, h41.y, accB1);
            accB1 = fmaf(wb1.z, h41.z, accB1);
            accB1 = fmaf(wb1.w, h41.w, accB1);
            float4 wa0 = __ldcs(vA + i);
            const int j0 = lead + 4 * i;
            accA0 = fmaf(wa0.x, sx[j0 + 0], accA0);
            accA0 = fmaf(wa0.y, sx[j0 + 1], accA0);
            accA0 = fmaf(wa0.z, sx[j0 + 2], accA0);
            accA0 = fmaf(wa0.w, sx[j0 + 3], accA0);
            float4 wa1 = __ldcs(vA + i + 32);
            const int j1 = j0 + 128;
            accA1 = fmaf(wa1.x, sx[j1 + 0], accA1);
            accA1 = fmaf(wa1.y, sx[j1 + 1], accA1);
            accA1 = fmaf(wa1.z, sx[j1 + 2], accA1);
            accA1 = fmaf(wa1.w, sx[j1 + 3], accA1);
        }
        // Tail: B vecs 960..1023 (2/lane), A vecs 960..nA-1 (predicated).
#pragma unroll
        for (int k = 0; k < 2; k++) {
            const int i = 960 + 32 * k + lane;
            float4 wb = rowB[i];
            float4 h4 = sv4[i];
            accB0 = fmaf(wb.x, h4.x, accB0);
            accB0 = fmaf(wb.y, h4.y, accB0);
            accB0 = fmaf(wb.z, h4.z, accB0);
            accB0 = fmaf(wb.w, h4.w, accB0);
            if (i < nA) {
                float4 wa = __ldcs(vA + i);
                const int j = lead + 4 * i;
                accA0 = fmaf(wa.x, sx[j + 0], accA0);
                accA0 = fmaf(wa.y, sx[j + 1], accA0);
                accA0 = fmaf(wa.z, sx[j + 2], accA0);
                accA0 = fmaf(wa.w, sx[j + 3], accA0);
            }
        }
        const int ts = lead + 4 * nA;
        if (lane < HD - ts) accA0 = fmaf(__ldcs(rowp + ts + lane), sx[ts + lane], accA0);

        float accA = warp_red(accA0 + accA1);
        float accB = warp_red(accB0 + accB1);
        z_reg     = accA + b_ih[r] + b_hh[r];
        whalt_reg = w_halt[r];
        if (lane == 0) {
            float hn = tanhf(z_reg + __ldcs(rowp - 1) + accB);
            __stcg(&g_h[0][r], hn);
            red[warp] = whalt_reg * hn;
        }
    } else if (lane == 0) {
        red[warp] = 0.f;
    }
    __syncthreads();
    if (tid == 0) {                     // fixed-order per-block partial
        float p = 0.f;
        for (int w = 0; w < nrows; w++) p += red[w];
        __stcg(&g_part[0][b], p);
    }
    grid_barrier();

    float cum = 0.f;
    int   t   = 0;

    for (;;) {
        // ---- Deterministic replicated halt decision ----
        if (warp == 0) {
            float a = 0.f;
#pragma unroll
            for (int i = lane; i < NBLK; i += 32) a += __ldcg(&g_part[t][i]);
            a = warp_red(a);
            if (lane == 0) bc = a;
        }
        __syncthreads();
        {
            float p = 1.f / (1.f + expf(-(bc + bhalt)));
            cum += p;
            if (cum >= 0.99f || t == MAXS - 1) break;
        }
        t++;

        // ---- W_out L2 prefetch, once, AFTER burst-A demand has drained:
        //      streams during the DRAM-idle step-1 window. ----
        if (t == 1) {
            const char* base = (const char*)(W_out + (size_t)r0 * HD);
            const size_t span = (size_t)nrows * HD * sizeof(float);
            for (size_t off = (size_t)tid * 128; off < span; off += (size_t)NTHR * 128)
                pf_l2(base + off);
        }

        // ---- Step t >= 1: h_t = tanh(z + W_hh @ h_{t-1})  (W_hh from L2) ----
        __syncthreads();
        {
            const float4* hold = (const float4*)g_h[(t - 1) & 1];
            float4* sv4 = (float4*)sv;
            for (int i = tid; i < HD / 4; i += NTHR) sv4[i] = __ldcg(&hold[i]);
        }
        __syncthreads();

        if (has_row) {
            const float4* row = (const float4*)(W_hh + (size_t)r * HD);
            const float4* hv4 = (const float4*)sv;
            float ah0 = 0.f, ah1 = 0.f;           // dual accumulators
#pragma unroll 8
            for (int i = lane; i < HD / 4; i += 64) {
                float4 w  = row[i];
                float4 h4 = hv4[i];
                ah0 = fmaf(w.x, h4.x, ah0);
                ah0 = fmaf(w.y, h4.y, ah0);
                ah0 = fmaf(w.z, h4.z, ah0);
                ah0 = fmaf(w.w, h4.w, ah0);
                float4 w2  = row[i + 32];
                float4 h42 = hv4[i + 32];
                ah1 = fmaf(w2.x, h42.x, ah1);
                ah1 = fmaf(w2.y, h42.y, ah1);
                ah1 = fmaf(w2.z, h42.z, ah1);
                ah1 = fmaf(w2.w, h42.w, ah1);
            }
            float ah = warp_red(ah0 + ah1);
            if (lane == 0) {
                float hn = tanhf(z_reg + ah);
                __stcg(&g_h[t & 1][r], hn);
                red[warp] = whalt_reg * hn;
            }
        } else if (lane == 0) {
            red[warp] = 0.f;
        }

        __syncthreads();
        if (tid == 0) {
            float p = 0.f;
            for (int w = 0; w < nrows; w++) p += red[w];
            __stcg(&g_part[t][b], p);
        }
        grid_barrier();
    }

    // ---- Final: output = W_out @ h[t] + b_out ; s_new = h[t] ; ponder = t ----
    __syncthreads();
    const float* hf = g_h[t & 1];
    {
        const float4* hf4 = (const float4*)hf;
        float4* sv4 = (float4*)sv;
        for (int i = tid; i < HD / 4; i += NTHR) sv4[i] = __ldcg(&hf4[i]);
    }
    __syncthreads();

    if (has_row) {
        const float4* row = (const float4*)(W_out + (size_t)r * HD);
        const float4* hv4 = (const float4*)sv;
        float ac0 = 0.f, ac1 = 0.f;               // dual accumulators
#pragma unroll 8
        for (int i = lane; i < HD / 4; i += 64) {
            float4 w  = __ldcs(row + i);   // read-once; hits L2 via tail prefetch
            float4 h4 = hv4[i];
            ac0 = fmaf(w.x, h4.x, ac0);
            ac0 = fmaf(w.y, h4.y, ac0);
            ac0 = fmaf(w.z, h4.z, ac0);
            ac0 = fmaf(w.w, h4.w, ac0);
            float4 w2  = __ldcs(row + i + 32);
            float4 h42 = hv4[i + 32];
            ac1 = fmaf(w2.x, h42.x, ac1);
            ac1 = fmaf(w2.y, h42.y, ac1);
            ac1 = fmaf(w2.z, h42.z, ac1);
            ac1 = fmaf(w2.w, h42.w, ac1);
        }
        float acc = warp_red(ac0 + ac1);
        if (lane == 0) out[r] = acc + b_out[r];
    }
    if (b == 0) {
        for (int i = tid; i < HD; i += NTHR) out[HD + i] = sv[i];
        if (tid == 0) out[2 * HD] = (float)t;
    }
}

extern "C" void kernel_launch(void* const* d_in, const int* in_sizes, int n_in,
                              void* d_out, int out_size) {
    (void)in_sizes; (void)n_in; (void)out_size;
    arnn_kernel<<<NBLK, NTHR>>>(
        (const float*)d_in[0],  // x
        (const float*)d_in[1],  // s
        (const float*)d_in[2],  // W_ih
        (const float*)d_in[3],  // b_ih
        (const float*)d_in[4],  // W_hh
        (const float*)d_in[5],  // b_hh
        (const float*)d_in[6],  // w_halt
        (const float*)d_in[7],  // b_halt
        (const float*)d_in[8],  // W_out
        (const float*)d_in[9],  // b_out
        (float*)d_out);
}

// round 14
// speedup vs baseline: 1.4606x; 1.1420x over previous
#include <cuda_runtime.h>
#include <math.h>

#define HD    4096
#define NBLK  148
#define NTHR  1024
#define NWARP (NTHR / 32)
#define MAXS  16

// Persistent-kernel state (allocation-free scratch).
__device__ float g_h[2][HD];             // double-buffered hidden state
__device__ float g_part[MAXS][NBLK];     // per-step per-block halt partial sums
__device__ unsigned g_barcnt;            // grid barrier arrival count
__device__ volatile unsigned g_bargen;   // grid barrier generation

__device__ __forceinline__ void grid_barrier() {
    __syncthreads();
    if (threadIdx.x == 0) {
        __threadfence();                       // release
        unsigned gen = g_bargen;
        if (atomicAdd(&g_barcnt, 1u) == NBLK - 1u) {
            g_barcnt = 0u;
            __threadfence();
            g_bargen = gen + 1u;
        } else {
            while (g_bargen == gen) { __nanosleep(16); }
        }
        __threadfence();                       // acquire
    }
    __syncthreads();
}

__device__ __forceinline__ float warp_red(float v) {
#pragma unroll
    for (int o = 16; o; o >>= 1) v += __shfl_xor_sync(0xffffffffu, v, o);
    return v;   // full sum on all lanes
}

__device__ __forceinline__ void pf_l2(const void* p) {
    asm volatile("prefetch.global.L2 [%0];" :: "l"(p));
}

__global__ void __launch_bounds__(NTHR, 1) arnn_kernel(
    const float* __restrict__ x,     const float* __restrict__ s,
    const float* __restrict__ W_ih,  const float* __restrict__ b_ih,
    const float* __restrict__ W_hh,  const float* __restrict__ b_hh,
    const float* __restrict__ w_halt,const float* __restrict__ b_halt,
    const float* __restrict__ W_out, const float* __restrict__ b_out,
    float* __restrict__ out)
{
    __shared__ float sx[HD];          // staged x (16 KB)
    __shared__ float sv[HD];          // staged h / s  (16 KB)
    __shared__ float red[NWARP];      // per-warp halt contributions
    __shared__ float bc;              // halt-sum broadcast

    const int tid  = threadIdx.x;
    const int lane = tid & 31;
    const int warp = tid >> 5;
    const int b    = blockIdx.x;

    // Balanced contiguous row ranges: every block gets 27-28 rows.
    const int r0    = (HD * b) / NBLK;
    const int r1    = (HD * (b + 1)) / NBLK;
    const int nrows = r1 - r0;
    const bool has_row = (warp < nrows);
    const int r     = r0 + warp;

    // ---- Stage x and s once (vectorized) ----
    {
        const float4* x4 = (const float4*)x;
        const float4* s4 = (const float4*)s;
        float4* sx4 = (float4*)sx;
        float4* sv4 = (float4*)sv;
        for (int i = tid; i < HD / 4; i += NTHR) { sx4[i] = x4[i]; sv4[i] = s4[i]; }
    }
    __syncthreads();

    const float bhalt = b_halt[0];
    float z_reg = 0.f, whalt_reg = 0.f;

    // ---- Fused phase-0 + step-0, dual-stream interleaved:
    //      z  = W_ih[:,1:] @ x + b_ih + b_hh   (evict-first stream)
    //      a0 = W_hh @ s                        (default: stays in L2 for step 1)
    //      h0 = tanh(z + W_ih[:,0] + a0)
    if (has_row) {
        const float* rowp = W_ih + (size_t)r * (HD + 1) + 1;   // misaligned by (r+1)&3
        const int mis  = (int)(((size_t)rowp >> 2) & 3);
        const int lead = (4 - mis) & 3;
        const float4* vA   = (const float4*)(rowp + lead);
        const float4* rowB = (const float4*)(W_hh + (size_t)r * HD);
        const float4* sv4  = (const float4*)sv;
        const int nA = (HD - lead) >> 2;                        // 1023 or 1024

        float accA = 0.f, accB = 0.f;
        if (lane < lead) accA = fmaf(__ldcs(rowp + lane), sx[lane], accA);

        // Branch-free main body: 992 vectors of each stream (31 iters/lane).
#pragma unroll 4
        for (int i = lane; i < 992; i += 32) {
            float4 wb = rowB[i];
            float4 h4 = sv4[i];
            accB = fmaf(wb.x, h4.x, accB);
            accB = fmaf(wb.y, h4.y, accB);
            accB = fmaf(wb.z, h4.z, accB);
            accB = fmaf(wb.w, h4.w, accB);
            float4 wa = __ldcs(vA + i);
            const int j = lead + 4 * i;
            accA = fmaf(wa.x, sx[j + 0], accA);
            accA = fmaf(wa.y, sx[j + 1], accA);
            accA = fmaf(wa.z, sx[j + 2], accA);
            accA = fmaf(wa.w, sx[j + 3], accA);
        }
        // Tail: B has 1024 vectors, A has 1023 (lead>0) or 1024 (lead==0).
        {
            const int i = 992 + lane;   // 992..1023
            float4 wb = rowB[i];
            float4 h4 = sv4[i];
            accB = fmaf(wb.x, h4.x, accB);
            accB = fmaf(wb.y, h4.y, accB);
            accB = fmaf(wb.z, h4.z, accB);
            accB = fmaf(wb.w, h4.w, accB);
            if (i < nA) {
                float4 wa = __ldcs(vA + i);
                const int j = lead + 4 * i;
                accA = fmaf(wa.x, sx[j + 0], accA);
                accA = fmaf(wa.y, sx[j + 1], accA);
                accA = fmaf(wa.z, sx[j + 2], accA);
                accA = fmaf(wa.w, sx[j + 3], accA);
            }
        }
        const int ts = lead + 4 * nA;
        if (lane < HD - ts) accA = fmaf(__ldcs(rowp + ts + lane), sx[ts + lane], accA);

        accA = warp_red(accA);
        accB = warp_red(accB);
        z_reg     = accA + b_ih[r] + b_hh[r];
        whalt_reg = w_halt[r];
        if (lane == 0) {
            float hn = tanhf(z_reg + __ldcs(rowp - 1) + accB);
            __stcg(&g_h[0][r], hn);
            red[warp] = whalt_reg * hn;
        }
    } else if (lane == 0) {
        red[warp] = 0.f;
    }
    __syncthreads();
    if (tid == 0) {                     // fixed-order per-block partial
        float p = 0.f;
        for (int w = 0; w < nrows; w++) p += red[w];
        __stcg(&g_part[0][b], p);
    }
    grid_barrier();

    float cum = 0.f;
    int   t   = 0;

    for (;;) {
        // ---- Deterministic replicated halt decision ----
        if (warp == 0) {
            float a = 0.f;
#pragma unroll
            for (int i = lane; i < NBLK; i += 32) a += __ldcg(&g_part[t][i]);
            a = warp_red(a);
            if (lane == 0) bc = a;
        }
        __syncthreads();
        {
            float p = 1.f / (1.f + expf(-(bc + bhalt)));
            cum += p;
            if (cum >= 0.99f || t == MAXS - 1) break;
        }
        t++;

        // ---- Step t >= 1: h_t = tanh(z + W_hh @ h_{t-1})  (W_hh from L2) ----
        __syncthreads();
        {
            const float4* hold = (const float4*)g_h[(t - 1) & 1];
            float4* sv4 = (float4*)sv;
            for (int i = tid; i < HD / 4; i += NTHR) sv4[i] = __ldcg(&hold[i]);
        }
        __syncthreads();

        if (has_row) {
            const float4* row = (const float4*)(W_hh + (size_t)r * HD);
            const float4* hv4 = (const float4*)sv;
            float ah = 0.f;
#pragma unroll 8
            for (int i = lane; i < HD / 4; i += 32) {
                float4 w  = row[i];
                float4 h4 = hv4[i];
                ah = fmaf(w.x, h4.x, ah);
                ah = fmaf(w.y, h4.y, ah);
                ah = fmaf(w.z, h4.z, ah);
                ah = fmaf(w.w, h4.w, ah);
            }
            ah = warp_red(ah);
            if (lane == 0) {
                float hn = tanhf(z_reg + ah);
                __stcg(&g_h[t & 1][r], hn);
                red[warp] = whalt_reg * hn;
            }
        } else if (lane == 0) {
            red[warp] = 0.f;
        }

        // ---- Prefetch this block's W_out rows into L2 (DRAM otherwise idle) ----
        {
            const char* base = (const char*)(W_out + (size_t)r0 * HD);
            const size_t span = (size_t)nrows * HD * sizeof(float);
            for (size_t off = (size_t)tid * 128; off < span; off += (size_t)NTHR * 128)
                pf_l2(base + off);
        }

        __syncthreads();
        if (tid == 0) {
            float p = 0.f;
            for (int w = 0; w < nrows; w++) p += red[w];
            __stcg(&g_part[t][b], p);
        }
        grid_barrier();
    }

    // ---- Final: output = W_out @ h[t] + b_out ; s_new = h[t] ; ponder = t ----
    __syncthreads();
    const float* hf = g_h[t & 1];
    {
        const float4* hf4 = (const float4*)hf;
        float4* sv4 = (float4*)sv;
        for (int i = tid; i < HD / 4; i += NTHR) sv4[i] = __ldcg(&hf4[i]);
    }
    __syncthreads();

    if (has_row) {
        const float4* row = (const float4*)(W_out + (size_t)r * HD);
        const float4* hv4 = (const float4*)sv;
        float acc = 0.f;
#pragma unroll 8
        for (int i = lane; i < HD / 4; i += 32) {
            float4 w  = __ldcs(row + i);   // read-once; hits L2 via prefetch
            float4 h4 = hv4[i];
            acc = fmaf(w.x, h4.x, acc);
            acc = fmaf(w.y, h4.y, acc);
            acc = fmaf(w.z, h4.z, acc);
            acc = fmaf(w.w, h4.w, acc);
        }
        acc = warp_red(acc);
        if (lane == 0) out[r] = acc + b_out[r];
    }
    if (b == 0) {
        for (int i = tid; i < HD; i += NTHR) out[HD + i] = sv[i];
        if (tid == 0) out[2 * HD] = (float)t;
    }
}

extern "C" void kernel_launch(void* const* d_in, const int* in_sizes, int n_in,
                              void* d_out, int out_size) {
    (void)in_sizes; (void)n_in; (void)out_size;
    arnn_kernel<<<NBLK, NTHR>>>(
        (const float*)d_in[0],  // x
        (const float*)d_in[1],  // s
        (const float*)d_in[2],  // W_ih
        (const float*)d_in[3],  // b_ih
        (const float*)d_in[4],  // W_hh
        (const float*)d_in[5],  // b_hh
        (const float*)d_in[6],  // w_halt
        (const float*)d_in[7],  // b_halt
        (const float*)d_in[8],  // W_out
        (const float*)d_in[9],  // b_out
        (float*)d_out);
}